// round 14
// baseline (speedup 1.0000x reference)
#include <cuda_runtime.h>
#include <cuda_fp16.h>
#include <cstdint>

#define BATCH 4096
#define IDIM  512
#define ODIM  512
#define NB    16
#define KBASE 8192
#define KEXT  8704

#define BM 64
#define BN 256
#define BK 128
#define NKT 68             /* k-iters per tile */
#define BASIS_T 64         /* absolute k-tiles < this: basis/weights; >=: silu */
#define NTHR 512
#define NTILES 128         /* 64 row-tiles x 2 col-strips */
#define GTOT (NTILES * NKT)/* 8704 global iter-units */
#define NCTA 148
#define TILE_A 16384       /* 64 rows x 128 halves x 2B */
#define TILE_BS 65536      /* 256 rows x 128 halves x 2B */

// -------------------- device scratch --------------------
__device__ __half g_Wh [(size_t)ODIM * KBASE];
__device__ __half g_BWh[(size_t)ODIM * IDIM];
__device__ float  g_xT [(size_t)IDIM * BATCH];
__device__ float  g_gemm[(size_t)BATCH * ODIM];

// -------------------- helpers --------------------
__device__ __forceinline__ uint32_t smem_u32(const void* p) {
    uint32_t a;
    asm("{ .reg .u64 t; cvta.to.shared.u64 t, %1; cvt.u32.u64 %0, t; }" : "=r"(a) : "l"(p));
    return a;
}
__device__ __forceinline__ void cp_async16(uint32_t dst, const void* src) {
    asm volatile("cp.async.cg.shared.global [%0], [%1], 16;" :: "r"(dst), "l"(src));
}
__device__ __forceinline__ uint32_t pack_h2(float a, float b) {
    __half2 h = __floats2half2_rn(a, b);
    return *reinterpret_cast<uint32_t*>(&h);
}
__device__ __forceinline__ float fast_exp_neg_sq(float z) {
    float e;
    asm("ex2.approx.f32 %0, %1;" : "=f"(e) : "f"(z * z * -1.44269504f));
    return e;
}

// -------------------- kernel 1: weights -> fp16 --------------------
__global__ void prep_w(const float* __restrict__ w, const float* __restrict__ bw) {
    const int NW = ODIM * KBASE / 8;
    const int NT = NW + ODIM * IDIM / 8;
    int i = blockIdx.x * blockDim.x + threadIdx.x;
    if (i >= NT) return;
    const float4* s; uint32_t* d; int j;
    if (i < NW) { s = (const float4*)w;  d = (uint32_t*)g_Wh;  j = i; }
    else        { s = (const float4*)bw; d = (uint32_t*)g_BWh; j = i - NW; }
    float4 a = s[2 * j], b = s[2 * j + 1];
    d[4 * j + 0] = pack_h2(a.x, a.y);
    d[4 * j + 1] = pack_h2(a.z, a.w);
    d[4 * j + 2] = pack_h2(b.x, b.y);
    d[4 * j + 3] = pack_h2(b.z, b.w);
}

// -------------------- kernel 2: transpose x --------------------
__global__ void prep_xt(const float* __restrict__ x) {
    __shared__ float t[32][33];
    int i0 = blockIdx.x * 32, b0 = blockIdx.y * 32;
    int tx = threadIdx.x, ty = threadIdx.y;
#pragma unroll
    for (int r = ty; r < 32; r += 8)
        t[r][tx] = x[(size_t)(b0 + r) * IDIM + i0 + tx];
    __syncthreads();
#pragma unroll
    for (int r = ty; r < 32; r += 8)
        g_xT[(size_t)(i0 + r) * BATCH + b0 + tx] = t[tx][r];
}

// -------------------- kernel 2b: zero the accumulator surface ------------
__global__ void zero_gemm() {
    int i = blockIdx.x * blockDim.x + threadIdx.x;
    ((float4*)g_gemm)[i] = make_float4(0.f, 0.f, 0.f, 0.f);
}

// -------------------- GEMM pieces --------------------
__device__ __forceinline__ void gen_basis(float xv, uint32_t vals[8]) {
    float z0 = (xv + 2.0f) * 3.75f;
    float v[16];
#pragma unroll
    for (int j = 0; j < 16; j++) v[j] = fast_exp_neg_sq(z0 - (float)j);
#pragma unroll
    for (int p = 0; p < 8; p++) vals[p] = pack_h2(v[2 * p], v[2 * p + 1]);
}
__device__ __forceinline__ void gen_silu16(int t, int row, int iq, int m0,
                                           uint32_t vals[8]) {
    int ibase = (t - BASIS_T) * 128 + iq * 16;
#pragma unroll
    for (int p = 0; p < 8; p++) {
        float a = g_xT[(size_t)(ibase + 2 * p)     * BATCH + m0 + row];
        float b = g_xT[(size_t)(ibase + 2 * p + 1) * BATCH + m0 + row];
        float ea, eb;
        asm("ex2.approx.f32 %0, %1;" : "=f"(ea) : "f"(a * -1.44269504f));
        asm("ex2.approx.f32 %0, %1;" : "=f"(eb) : "f"(b * -1.44269504f));
        vals[p] = pack_h2(a / (1.0f + ea), b / (1.0f + eb));
    }
}
__device__ __forceinline__ void sts_vals(uint32_t aBase, int row, int iq,
                                         const uint32_t vals[8]) {
#pragma unroll
    for (int c = 0; c < 2; c++) {
        uint32_t u = row * 16 + ((iq * 2 + c) ^ (row & 7));   // 16B units
        asm volatile("st.shared.v4.b32 [%0], {%1,%2,%3,%4};"
                     :: "r"(aBase + u * 16),
                        "r"(vals[4 * c]), "r"(vals[4 * c + 1]),
                        "r"(vals[4 * c + 2]), "r"(vals[4 * c + 3]) : "memory");
    }
}
__device__ __forceinline__ void cp_B(int t, uint32_t bBase, int tid, int n0) {
    const __half* src; int ldb, ko;
    if (t < BASIS_T) { src = g_Wh;  ldb = KBASE; ko = t * BK; }
    else             { src = g_BWh; ldb = IDIM;  ko = (t - BASIS_T) * BK; }
#pragma unroll
    for (int q = 0; q < 8; q++) {
        int c   = tid + NTHR * q;
        int r   = c >> 4, u16 = c & 15;
        uint32_t u = r * 16 + (u16 ^ (r & 7));
        cp_async16(bBase + u * 16, src + (size_t)(n0 + r) * ldb + ko + u16 * 8);
    }
}

#define LDSM_X4(R, ADDR)                                                        \
    asm volatile("ldmatrix.sync.aligned.m8n8.x4.shared.b16 {%0,%1,%2,%3}, [%4];"\
                 : "=r"((R)[0]), "=r"((R)[1]), "=r"((R)[2]), "=r"((R)[3])       \
                 : "r"(ADDR))

#define MMA16816(ACC, A, B0, B1)                                                \
    asm volatile("mma.sync.aligned.m16n8k16.row.col.f32.f16.f16.f32 "           \
                 "{%0,%1,%2,%3}, {%4,%5,%6,%7}, {%8,%9}, {%0,%1,%2,%3};"        \
                 : "+f"((ACC)[0]), "+f"((ACC)[1]), "+f"((ACC)[2]), "+f"((ACC)[3])\
                 : "r"((A)[0]), "r"((A)[1]), "r"((A)[2]), "r"((A)[3]),          \
                   "r"(B0), "r"(B1))

__global__ void __launch_bounds__(NTHR, 1)
gemm_kernel() {
    extern __shared__ __align__(1024) char sm[];
    const uint32_t sb  = smem_u32(sm);
    const uint32_t sbA = sb;                    // 2 x 16 KB
    const uint32_t sbB = sb + 2 * TILE_A;       // 2 x 64 KB

    const int tid  = threadIdx.x;
    const int lane = tid & 31;
    const int wid  = tid >> 5;                  // 0..15
    const int wm   = wid >> 3;                  // 0..1: 32 rows each
    const int wn   = wid & 7;                   // 0..7: 32 cols each
    const int row  = tid & 63;
    const int iq   = tid >> 6;                  // 0..7
    // phase skew: alternates WITHIN each SMSP (warps s, s+4, s+8, s+12 -> 0,1,0,1)
    const int skew = (wid >> 2) & 1;

    const int cta  = blockIdx.x;
    int g          = (GTOT * cta) / NCTA;
    const int gend = (GTOT * (cta + 1)) / NCTA;

    while (g < gend) {
        const int tt   = g / NKT;
        const int l0   = g - tt * NKT;
        const int lend = min(NKT, gend - tt * NKT);
        const int m0   = (tt & 63) * BM;
        const int n0   = (tt >> 6) * BN;

        float acc[2][4][4] = {};
        uint32_t vals[8];
        float xv = 0.0f;

        // ---- segment prologue: A(l0) gen+store, B(l0) cp
        if (l0 < BASIS_T) {
            float x0 = g_xT[(size_t)(l0 * 8 + iq) * BATCH + m0 + row];
            gen_basis(x0, vals);
        } else {
            gen_silu16(l0, row, iq, m0, vals);
        }
        sts_vals(sbA + (l0 & 1) * TILE_A, row, iq, vals);
        cp_B(l0, sbB + (l0 & 1) * TILE_BS, tid, n0);
        asm volatile("cp.async.commit_group;");
        if (l0 + 1 < lend && l0 + 1 < BASIS_T)
            xv = g_xT[(size_t)((l0 + 1) * 8 + iq) * BATCH + m0 + row];
        asm volatile("cp.async.wait_group 0;");
        __syncthreads();

        for (int t = l0; t < lend; t++) {
            const uint32_t aB = sbA + (t & 1) * TILE_A;
            const uint32_t bB = sbB + (t & 1) * TILE_BS;
            const bool havenext = (t + 1 < lend);

            // 1) B(t+1) — async issue, all warps, cheap
            if (havenext) {
                cp_B(t + 1, sbB + ((t + 1) & 1) * TILE_BS, tid, n0);
                asm volatile("cp.async.commit_group;");
            }

            // ---- phase-skewed body: half of each SMSP's warps do MMA first,
            //      the other half do gen/STS first, so MUFU/LSU overlap tensor.
#define GEN_PHASE()                                                            \
            do {                                                               \
                if (havenext) {                                                \
                    if (t + 1 < BASIS_T) gen_basis(xv, vals);                  \
                    else                 gen_silu16(t + 1, row, iq, m0, vals); \
                    sts_vals(sbA + ((t + 1) & 1) * TILE_A, row, iq, vals);     \
                }                                                              \
                if (t + 2 < lend && t + 2 < BASIS_T)                           \
                    xv = g_xT[(size_t)((t + 2) * 8 + iq) * BATCH + m0 + row];  \
            } while (0)

#define MMA_PHASE()                                                            \
            do {                                                               \
                _Pragma("unroll")                                              \
                for (int ks = 0; ks < 8; ks++) {                               \
                    const int c16 = ks * 2 + (lane >> 4);                      \
                    uint32_t af[2][4], bf[2][4];                               \
                    _Pragma("unroll")                                          \
                    for (int mi = 0; mi < 2; mi++) {                           \
                        int r = wm * 32 + mi * 16 + (lane & 15);               \
                        uint32_t u = r * 16 + (c16 ^ (r & 7));                 \
                        LDSM_X4(af[mi], aB + u * 16);                          \
                    }                                                          \
                    _Pragma("unroll")                                          \
                    for (int nj = 0; nj < 2; nj++) {                           \
                        int r = wn * 32 + nj * 16 + (lane & 15);               \
                        uint32_t u = r * 16 + (c16 ^ (r & 7));                 \
                        LDSM_X4(bf[nj], bB + u * 16);                          \
                    }                                                          \
                    _Pragma("unroll")                                          \
                    for (int mi = 0; mi < 2; mi++)                             \
                        _Pragma("unroll")                                      \
                        for (int nj = 0; nj < 2; nj++) {                       \
                            MMA16816(acc[mi][2 * nj],     af[mi], bf[nj][0], bf[nj][2]); \
                            MMA16816(acc[mi][2 * nj + 1], af[mi], bf[nj][1], bf[nj][3]); \
                        }                                                      \
                }                                                              \
            } while (0)

            if (skew) {
                GEN_PHASE();
                MMA_PHASE();
            } else {
                MMA_PHASE();
                GEN_PHASE();
            }
#undef GEN_PHASE
#undef MMA_PHASE

            asm volatile("cp.async.wait_group 0;");   // B(t+1) resident
            __syncthreads();                          // A(t+1) visible; buffers swap
        }

        // ---- segment epilogue: commit partial sums
#pragma unroll
        for (int mi = 0; mi < 2; mi++)
#pragma unroll
            for (int ni = 0; ni < 4; ni++) {
                int r = m0 + wm * 32 + mi * 16 + (lane >> 2);
                int c = n0 + wn * 32 + ni * 8 + (lane & 3) * 2;
                atomicAdd(&g_gemm[(size_t)r * ODIM + c],           acc[mi][ni][0]);
                atomicAdd(&g_gemm[(size_t)r * ODIM + c + 1],       acc[mi][ni][1]);
                atomicAdd(&g_gemm[(size_t)(r + 8) * ODIM + c],     acc[mi][ni][2]);
                atomicAdd(&g_gemm[(size_t)(r + 8) * ODIM + c + 1], acc[mi][ni][3]);
            }

        g = tt * NKT + lend;
    }
}

// -------------------- kernel 4: LayerNorm --------------------
__global__ void ln_kernel(const float* __restrict__ gamma,
                          const float* __restrict__ beta,
                          float* __restrict__ out) {
    int warp = threadIdx.x >> 5, lane = threadIdx.x & 31;
    int row = blockIdx.x * 8 + warp;
    const float4* src = (const float4*)&g_gemm[(size_t)row * ODIM];
    float4 v[4];
    float s = 0.0f, s2 = 0.0f;
#pragma unroll
    for (int i = 0; i < 4; i++) {
        v[i] = src[i * 32 + lane];
        s  += v[i].x + v[i].y + v[i].z + v[i].w;
        s2 += v[i].x*v[i].x + v[i].y*v[i].y + v[i].z*v[i].z + v[i].w*v[i].w;
    }
#pragma unroll
    for (int o = 16; o > 0; o >>= 1) {
        s  += __shfl_xor_sync(0xFFFFFFFFu, s,  o);
        s2 += __shfl_xor_sync(0xFFFFFFFFu, s2, o);
    }
    float mean = s * (1.0f / ODIM);
    float var  = s2 * (1.0f / ODIM) - mean * mean;
    float rstd = rsqrtf(var + 1e-5f);
    const float4* g4 = (const float4*)gamma;
    const float4* b4 = (const float4*)beta;
    float4* dst = (float4*)&out[(size_t)row * ODIM];
#pragma unroll
    for (int i = 0; i < 4; i++) {
        int c4 = i * 32 + lane;
        float4 gm = g4[c4], bt = b4[c4], r;
        r.x = (v[i].x - mean) * rstd * gm.x + bt.x;
        r.y = (v[i].y - mean) * rstd * gm.y + bt.y;
        r.z = (v[i].z - mean) * rstd * gm.z + bt.z;
        r.w = (v[i].w - mean) * rstd * gm.w + bt.w;
        dst[c4] = r;
    }
}

// ---------------------------------------------------------------------------
extern "C" void kernel_launch(void* const* d_in, const int* in_sizes, int n_in,
                              void* d_out, int out_size) {
    const float* x      = (const float*)d_in[0];
    const float* wts    = (const float*)d_in[1];
    const float* base_w = (const float*)d_in[2];
    const float* gamma  = (const float*)d_in[3];
    const float* beta   = (const float*)d_in[4];
    float* out = (float*)d_out;

    prep_w<<<(ODIM * KBASE / 8 + ODIM * IDIM / 8 + 255) / 256, 256>>>(wts, base_w);
    prep_xt<<<dim3(IDIM / 32, BATCH / 32), dim3(32, 8)>>>(x);
    zero_gemm<<<(BATCH * ODIM / 4) / 256, 256>>>();

    int smem_bytes = 2 * TILE_A + 2 * TILE_BS;   // 160 KB
    cudaFuncSetAttribute(gemm_kernel, cudaFuncAttributeMaxDynamicSharedMemorySize,
                         smem_bytes);
    gemm_kernel<<<NCTA, NTHR, smem_bytes>>>();

    ln_kernel<<<BATCH / 8, 256>>>(gamma, beta, out);
}

// round 15
// speedup vs baseline: 1.0040x; 1.0040x over previous
#include <cuda_runtime.h>
#include <cuda_fp16.h>
#include <cstdint>

#define BATCH 4096
#define IDIM  512
#define ODIM  512
#define NB    16
#define KBASE 8192
#define KEXT  8704

#define BM 64
#define BN 256
#define BK 128
#define NKT 68             /* k-iters per tile */
#define BASIS_T 64         /* absolute k-tiles < this: basis/weights; >=: silu */
#define NTHR 512
#define NTILES 128         /* 64 row-tiles x 2 col-strips */
#define GTOT (NTILES * NKT)/* 8704 global iter-units */
#define NCTA 148
#define TILE_A 16384       /* 64 rows x 128 halves x 2B */
#define TILE_BS 65536      /* 256 rows x 128 halves x 2B */

// -------------------- device scratch --------------------
__device__ __half g_Wh [(size_t)ODIM * KBASE];
__device__ __half g_BWh[(size_t)ODIM * IDIM];
__device__ float  g_xT [(size_t)IDIM * BATCH];
__device__ float  g_gemm[(size_t)BATCH * ODIM];

// -------------------- helpers --------------------
__device__ __forceinline__ uint32_t smem_u32(const void* p) {
    uint32_t a;
    asm("{ .reg .u64 t; cvta.to.shared.u64 t, %1; cvt.u32.u64 %0, t; }" : "=r"(a) : "l"(p));
    return a;
}
__device__ __forceinline__ void cp_async16(uint32_t dst, const void* src) {
    asm volatile("cp.async.cg.shared.global [%0], [%1], 16;" :: "r"(dst), "l"(src));
}
__device__ __forceinline__ uint32_t pack_h2(float a, float b) {
    __half2 h = __floats2half2_rn(a, b);
    return *reinterpret_cast<uint32_t*>(&h);
}
__device__ __forceinline__ float fast_exp_neg_sq(float z) {
    float e;
    asm("ex2.approx.f32 %0, %1;" : "=f"(e) : "f"(z * z * -1.44269504f));
    return e;
}

// -------------------- kernel 1: weights -> fp16 --------------------
__global__ void prep_w(const float* __restrict__ w, const float* __restrict__ bw) {
    const int NW = ODIM * KBASE / 8;
    const int NT = NW + ODIM * IDIM / 8;
    int i = blockIdx.x * blockDim.x + threadIdx.x;
    if (i >= NT) return;
    const float4* s; uint32_t* d; int j;
    if (i < NW) { s = (const float4*)w;  d = (uint32_t*)g_Wh;  j = i; }
    else        { s = (const float4*)bw; d = (uint32_t*)g_BWh; j = i - NW; }
    float4 a = s[2 * j], b = s[2 * j + 1];
    d[4 * j + 0] = pack_h2(a.x, a.y);
    d[4 * j + 1] = pack_h2(a.z, a.w);
    d[4 * j + 2] = pack_h2(b.x, b.y);
    d[4 * j + 3] = pack_h2(b.z, b.w);
}

// -------------------- kernel 2: transpose x --------------------
__global__ void prep_xt(const float* __restrict__ x) {
    __shared__ float t[32][33];
    int i0 = blockIdx.x * 32, b0 = blockIdx.y * 32;
    int tx = threadIdx.x, ty = threadIdx.y;
#pragma unroll
    for (int r = ty; r < 32; r += 8)
        t[r][tx] = x[(size_t)(b0 + r) * IDIM + i0 + tx];
    __syncthreads();
#pragma unroll
    for (int r = ty; r < 32; r += 8)
        g_xT[(size_t)(i0 + r) * BATCH + b0 + tx] = t[tx][r];
}

// -------------------- kernel 2b: zero the accumulator surface ------------
__global__ void zero_gemm() {
    int i = blockIdx.x * blockDim.x + threadIdx.x;
    ((float4*)g_gemm)[i] = make_float4(0.f, 0.f, 0.f, 0.f);
}

// -------------------- GEMM pieces --------------------
__device__ __forceinline__ void gen_basis(float xv, uint32_t vals[8]) {
    float z0 = (xv + 2.0f) * 3.75f;
    float v[16];
#pragma unroll
    for (int j = 0; j < 16; j++) v[j] = fast_exp_neg_sq(z0 - (float)j);
#pragma unroll
    for (int p = 0; p < 8; p++) vals[p] = pack_h2(v[2 * p], v[2 * p + 1]);
}
__device__ __forceinline__ void gen_silu16(int t, int row, int iq, int m0,
                                           uint32_t vals[8]) {
    int ibase = (t - BASIS_T) * 128 + iq * 16;
#pragma unroll
    for (int p = 0; p < 8; p++) {
        float a = g_xT[(size_t)(ibase + 2 * p)     * BATCH + m0 + row];
        float b = g_xT[(size_t)(ibase + 2 * p + 1) * BATCH + m0 + row];
        float ea, eb;
        asm("ex2.approx.f32 %0, %1;" : "=f"(ea) : "f"(a * -1.44269504f));
        asm("ex2.approx.f32 %0, %1;" : "=f"(eb) : "f"(b * -1.44269504f));
        vals[p] = pack_h2(a / (1.0f + ea), b / (1.0f + eb));
    }
}
// sts with hoisted swizzle: caller passes sOff = row*256 + (((iq*2)^(row&7))<<4)
__device__ __forceinline__ void sts_vals(uint32_t addr0, const uint32_t vals[8]) {
    asm volatile("st.shared.v4.b32 [%0], {%1,%2,%3,%4};"
                 :: "r"(addr0),
                    "r"(vals[0]), "r"(vals[1]), "r"(vals[2]), "r"(vals[3]) : "memory");
    asm volatile("st.shared.v4.b32 [%0], {%1,%2,%3,%4};"
                 :: "r"(addr0 ^ 16u),
                    "r"(vals[4]), "r"(vals[5]), "r"(vals[6]), "r"(vals[7]) : "memory");
}
// cp_B with hoisted offsets: uOff = thread's swizzled smem offset for q=0,
// gRow = row for q=0; per q: smem += 8192, gmem row += 32.
__device__ __forceinline__ void cp_B(int t, uint32_t bBase, uint32_t uOff,
                                     int gRow, int gCol, int n0) {
    const __half* src; int ldb, ko;
    if (t < BASIS_T) { src = g_Wh;  ldb = KBASE; ko = t * BK; }
    else             { src = g_BWh; ldb = IDIM;  ko = (t - BASIS_T) * BK; }
    const __half* gp = src + (size_t)(n0 + gRow) * ldb + ko + gCol;
#pragma unroll
    for (int q = 0; q < 8; q++)
        cp_async16(bBase + uOff + q * 8192u, gp + (size_t)(32 * q) * ldb);
}

#define LDSM_X4(R, ADDR)                                                        \
    asm volatile("ldmatrix.sync.aligned.m8n8.x4.shared.b16 {%0,%1,%2,%3}, [%4];"\
                 : "=r"((R)[0]), "=r"((R)[1]), "=r"((R)[2]), "=r"((R)[3])       \
                 : "r"(ADDR))

#define MMA16816(ACC, A, B0, B1)                                                \
    asm volatile("mma.sync.aligned.m16n8k16.row.col.f32.f16.f16.f32 "           \
                 "{%0,%1,%2,%3}, {%4,%5,%6,%7}, {%8,%9}, {%0,%1,%2,%3};"        \
                 : "+f"((ACC)[0]), "+f"((ACC)[1]), "+f"((ACC)[2]), "+f"((ACC)[3])\
                 : "r"((A)[0]), "r"((A)[1]), "r"((A)[2]), "r"((A)[3]),          \
                   "r"(B0), "r"(B1))

__global__ void __launch_bounds__(NTHR, 1)
gemm_kernel() {
    extern __shared__ __align__(1024) char sm[];
    const uint32_t sb  = smem_u32(sm);
    const uint32_t sbA = sb;                    // 2 x 16 KB
    const uint32_t sbB = sb + 2 * TILE_A;       // 2 x 64 KB

    const int tid  = threadIdx.x;
    const int lane = tid & 31;
    const int wid  = tid >> 5;                  // 0..15
    const int wm   = wid >> 3;                  // 0..1: 32 rows each
    const int wn   = wid & 7;                   // 0..7: 32 cols each
    const int row  = tid & 63;
    const int iq   = tid >> 6;                  // 0..7

    // ---- hoisted swizzled-address bases (iteration-invariant pieces) ----
    // LDSM: addr(ks) = [buf + r*256 + ((e^(r&7))<<4)] ^ (ks<<5); mi adds 4096.
    const uint32_t e   = (uint32_t)(lane >> 4);
    const int rA0 = wm * 32 + (lane & 15);
    const int rB0 = wn * 32 + (lane & 15);
    const uint32_t swA = (uint32_t)rA0 * 256u + ((e ^ (uint32_t)(rA0 & 7)) << 4);
    const uint32_t swB = (uint32_t)rB0 * 256u + ((e ^ (uint32_t)(rB0 & 7)) << 4);
    // A-store: addr(c) = [buf + row*256 + (((iq*2)^(row&7))<<4)] ^ (c<<4)
    const uint32_t stA = (uint32_t)row * 256u +
                         (((uint32_t)(iq * 2) ^ (uint32_t)(row & 7)) << 4);
    // cp_B: q=0 offsets
    const uint32_t cpU = (uint32_t)(tid >> 4) * 256u +
                         (((uint32_t)(tid & 15) ^ (uint32_t)((tid >> 4) & 7)) << 4);
    const int cpRow = tid >> 4;
    const int cpCol = (tid & 15) * 8;

    const int cta  = blockIdx.x;
    int g          = (GTOT * cta) / NCTA;
    const int gend = (GTOT * (cta + 1)) / NCTA;

    while (g < gend) {
        const int tt   = g / NKT;
        const int l0   = g - tt * NKT;
        const int lend = min(NKT, gend - tt * NKT);
        const int m0   = (tt & 63) * BM;
        const int n0   = (tt >> 6) * BN;

        float acc[2][4][4] = {};
        uint32_t vals[8];
        float xv = 0.0f;

        // ---- segment prologue: A(l0) gen+store, B(l0) cp
        if (l0 < BASIS_T) {
            float x0 = g_xT[(size_t)(l0 * 8 + iq) * BATCH + m0 + row];
            gen_basis(x0, vals);
        } else {
            gen_silu16(l0, row, iq, m0, vals);
        }
        sts_vals(sbA + (l0 & 1) * TILE_A + stA, vals);
        cp_B(l0, sbB + (l0 & 1) * TILE_BS, cpU, cpRow, cpCol, n0);
        asm volatile("cp.async.commit_group;");
        if (l0 + 1 < lend && l0 + 1 < BASIS_T)
            xv = g_xT[(size_t)((l0 + 1) * 8 + iq) * BATCH + m0 + row];
        asm volatile("cp.async.wait_group 0;");
        __syncthreads();

        for (int t = l0; t < lend; t++) {
            const uint32_t pA = sbA + (t & 1) * TILE_A  + swA;
            const uint32_t pB = sbB + (t & 1) * TILE_BS + swB;

            // 1) B(t+1) into the other buffer
            if (t + 1 < lend) {
                cp_B(t + 1, sbB + ((t + 1) & 1) * TILE_BS, cpU, cpRow, cpCol, n0);
                asm volatile("cp.async.commit_group;");
            }
            // 2) generate A(t+1) into regs
            if (t + 1 < lend) {
                if (t + 1 < BASIS_T) gen_basis(xv, vals);
                else                 gen_silu16(t + 1, row, iq, m0, vals);
            }

            // 3) MMA over this k-tile: addresses are pX ^ (ks<<5) — 1 LOP3 each
#pragma unroll
            for (int ks = 0; ks < 8; ks++) {
                const uint32_t kx = (uint32_t)(ks << 5);
                uint32_t af[2][4], bf[2][4];
                LDSM_X4(af[0], pA ^ kx);
                LDSM_X4(af[1], (pA + 4096u) ^ kx);
                LDSM_X4(bf[0], pB ^ kx);
                LDSM_X4(bf[1], (pB + 4096u) ^ kx);
#pragma unroll
                for (int mi = 0; mi < 2; mi++)
#pragma unroll
                    for (int nj = 0; nj < 2; nj++) {
                        MMA16816(acc[mi][2 * nj],     af[mi], bf[nj][0], bf[nj][2]);
                        MMA16816(acc[mi][2 * nj + 1], af[mi], bf[nj][1], bf[nj][3]);
                    }
            }

            // 4) store A(t+1) into the other A buffer
            if (t + 1 < lend)
                sts_vals(sbA + ((t + 1) & 1) * TILE_A + stA, vals);
            // 5) prefetch x for tile t+2
            if (t + 2 < lend && t + 2 < BASIS_T)
                xv = g_xT[(size_t)((t + 2) * 8 + iq) * BATCH + m0 + row];

            asm volatile("cp.async.wait_group 0;");   // B(t+1) resident
            __syncthreads();                          // A(t+1) visible; buffers swap
        }

        // ---- segment epilogue: commit partial sums
#pragma unroll
        for (int mi = 0; mi < 2; mi++)
#pragma unroll
            for (int ni = 0; ni < 4; ni++) {
                int r = m0 + wm * 32 + mi * 16 + (lane >> 2);
                int c = n0 + wn * 32 + ni * 8 + (lane & 3) * 2;
                atomicAdd(&g_gemm[(size_t)r * ODIM + c],           acc[mi][ni][0]);
                atomicAdd(&g_gemm[(size_t)r * ODIM + c + 1],       acc[mi][ni][1]);
                atomicAdd(&g_gemm[(size_t)(r + 8) * ODIM + c],     acc[mi][ni][2]);
                atomicAdd(&g_gemm[(size_t)(r + 8) * ODIM + c + 1], acc[mi][ni][3]);
            }

        g = tt * NKT + lend;
    }
}

// -------------------- kernel 4: LayerNorm --------------------
__global__ void ln_kernel(const float* __restrict__ gamma,
                          const float* __restrict__ beta,
                          float* __restrict__ out) {
    int warp = threadIdx.x >> 5, lane = threadIdx.x & 31;
    int row = blockIdx.x * 8 + warp;
    const float4* src = (const float4*)&g_gemm[(size_t)row * ODIM];
    float4 v[4];
    float s = 0.0f, s2 = 0.0f;
#pragma unroll
    for (int i = 0; i < 4; i++) {
        v[i] = src[i * 32 + lane];
        s  += v[i].x + v[i].y + v[i].z + v[i].w;
        s2 += v[i].x*v[i].x + v[i].y*v[i].y + v[i].z*v[i].z + v[i].w*v[i].w;
    }
#pragma unroll
    for (int o = 16; o > 0; o >>= 1) {
        s  += __shfl_xor_sync(0xFFFFFFFFu, s,  o);
        s2 += __shfl_xor_sync(0xFFFFFFFFu, s2, o);
    }
    float mean = s * (1.0f / ODIM);
    float var  = s2 * (1.0f / ODIM) - mean * mean;
    float rstd = rsqrtf(var + 1e-5f);
    const float4* g4 = (const float4*)gamma;
    const float4* b4 = (const float4*)beta;
    float4* dst = (float4*)&out[(size_t)row * ODIM];
#pragma unroll
    for (int i = 0; i < 4; i++) {
        int c4 = i * 32 + lane;
        float4 gm = g4[c4], bt = b4[c4], r;
        r.x = (v[i].x - mean) * rstd * gm.x + bt.x;
        r.y = (v[i].y - mean) * rstd * gm.y + bt.y;
        r.z = (v[i].z - mean) * rstd * gm.z + bt.z;
        r.w = (v[i].w - mean) * rstd * gm.w + bt.w;
        dst[c4] = r;
    }
}

// ---------------------------------------------------------------------------
extern "C" void kernel_launch(void* const* d_in, const int* in_sizes, int n_in,
                              void* d_out, int out_size) {
    const float* x      = (const float*)d_in[0];
    const float* wts    = (const float*)d_in[1];
    const float* base_w = (const float*)d_in[2];
    const float* gamma  = (const float*)d_in[3];
    const float* beta   = (const float*)d_in[4];
    float* out = (float*)d_out;

    prep_w<<<(ODIM * KBASE / 8 + ODIM * IDIM / 8 + 255) / 256, 256>>>(wts, base_w);
    prep_xt<<<dim3(IDIM / 32, BATCH / 32), dim3(32, 8)>>>(x);
    zero_gemm<<<(BATCH * ODIM / 4) / 256, 256>>>();

    int smem_bytes = 2 * TILE_A + 2 * TILE_BS;   // 160 KB
    cudaFuncSetAttribute(gemm_kernel, cudaFuncAttributeMaxDynamicSharedMemorySize,
                         smem_bytes);
    gemm_kernel<<<NCTA, NTHR, smem_bytes>>>();

    ln_kernel<<<BATCH / 8, 256>>>(gamma, beta, out);
}

// round 16
// speedup vs baseline: 1.0606x; 1.0564x over previous
#include <cuda_runtime.h>
#include <cuda_fp16.h>
#include <cstdint>

#define BATCH 4096
#define IDIM  512
#define ODIM  512
#define NB    16
#define KBASE 8192
#define KEXT  8704

#define BM 64
#define BN 256
#define BK 128
#define NKT 68             /* k-iters per tile */
#define BASIS_T 64         /* absolute k-tiles < this: basis/weights; >=: silu */
#define NTHR 512
#define NTILES 128         /* 64 row-tiles x 2 col-strips */
#define GTOT (NTILES * NKT)/* 8704 global iter-units */
#define NCTA 148
#define TILE_A 16384       /* 64 rows x 128 halves x 2B */
#define TILE_BS 65536      /* 256 rows x 128 halves x 2B */

/* fused prep kernel block ranges (256 threads each) */
#define PW_BLOCKS 2176     /* (512*8192/8 + 512*512/8) / 256 */
#define XT_BLOCKS 2048     /* 16 x 128 tiles of 32x32 */
#define ZG_BLOCKS 2048     /* 4096*512/4/256 */

// -------------------- device scratch --------------------
__device__ __half g_Wh [(size_t)ODIM * KBASE];
__device__ __half g_BWh[(size_t)ODIM * IDIM];
__device__ float  g_xT [(size_t)IDIM * BATCH];
__device__ float  g_gemm[(size_t)BATCH * ODIM];

// -------------------- helpers --------------------
__device__ __forceinline__ uint32_t smem_u32(const void* p) {
    uint32_t a;
    asm("{ .reg .u64 t; cvta.to.shared.u64 t, %1; cvt.u32.u64 %0, t; }" : "=r"(a) : "l"(p));
    return a;
}
__device__ __forceinline__ void cp_async16(uint32_t dst, const void* src) {
    asm volatile("cp.async.cg.shared.global [%0], [%1], 16;" :: "r"(dst), "l"(src));
}
__device__ __forceinline__ uint32_t pack_h2(float a, float b) {
    __half2 h = __floats2half2_rn(a, b);
    return *reinterpret_cast<uint32_t*>(&h);
}
__device__ __forceinline__ float fast_exp_neg_sq(float z) {
    float e;
    asm("ex2.approx.f32 %0, %1;" : "=f"(e) : "f"(z * z * -1.44269504f));
    return e;
}
__device__ __forceinline__ void red_add(float* p, float v) {
    asm volatile("red.global.add.f32 [%0], %1;" :: "l"(p), "f"(v) : "memory");
}

// -------------------- fused prep: weights->fp16 | x transpose | zero ------
__global__ void prep_all(const float* __restrict__ w, const float* __restrict__ bw,
                         const float* __restrict__ x) {
    int b = blockIdx.x;
    if (b < PW_BLOCKS) {
        const int NW = ODIM * KBASE / 8;
        const int NT = NW + ODIM * IDIM / 8;
        int i = b * 256 + threadIdx.x;
        if (i >= NT) return;
        const float4* s; uint32_t* d; int j;
        if (i < NW) { s = (const float4*)w;  d = (uint32_t*)g_Wh;  j = i; }
        else        { s = (const float4*)bw; d = (uint32_t*)g_BWh; j = i - NW; }
        float4 a = s[2 * j], c = s[2 * j + 1];
        d[4 * j + 0] = pack_h2(a.x, a.y);
        d[4 * j + 1] = pack_h2(a.z, a.w);
        d[4 * j + 2] = pack_h2(c.x, c.y);
        d[4 * j + 3] = pack_h2(c.z, c.w);
    } else if (b < PW_BLOCKS + XT_BLOCKS) {
        __shared__ float t[32][33];
        int bb = b - PW_BLOCKS;
        int i0 = (bb & 15) * 32, b0 = (bb >> 4) * 32;
        int tx = threadIdx.x & 31, ty = threadIdx.x >> 5;   // 32 x 8
#pragma unroll
        for (int r = ty; r < 32; r += 8)
            t[r][tx] = x[(size_t)(b0 + r) * IDIM + i0 + tx];
        __syncthreads();
#pragma unroll
        for (int r = ty; r < 32; r += 8)
            g_xT[(size_t)(i0 + r) * BATCH + b0 + tx] = t[tx][r];
    } else {
        int i = (b - PW_BLOCKS - XT_BLOCKS) * 256 + threadIdx.x;
        ((float4*)g_gemm)[i] = make_float4(0.f, 0.f, 0.f, 0.f);
    }
}

// -------------------- GEMM pieces (exact R10) --------------------
__device__ __forceinline__ void gen_basis(float xv, uint32_t vals[8]) {
    float z0 = (xv + 2.0f) * 3.75f;
    float v[16];
#pragma unroll
    for (int j = 0; j < 16; j++) v[j] = fast_exp_neg_sq(z0 - (float)j);
#pragma unroll
    for (int p = 0; p < 8; p++) vals[p] = pack_h2(v[2 * p], v[2 * p + 1]);
}
__device__ __forceinline__ void gen_silu16(int t, int row, int iq, int m0,
                                           uint32_t vals[8]) {
    int ibase = (t - BASIS_T) * 128 + iq * 16;
#pragma unroll
    for (int p = 0; p < 8; p++) {
        float a = g_xT[(size_t)(ibase + 2 * p)     * BATCH + m0 + row];
        float b = g_xT[(size_t)(ibase + 2 * p + 1) * BATCH + m0 + row];
        float ea, eb;
        asm("ex2.approx.f32 %0, %1;" : "=f"(ea) : "f"(a * -1.44269504f));
        asm("ex2.approx.f32 %0, %1;" : "=f"(eb) : "f"(b * -1.44269504f));
        vals[p] = pack_h2(a / (1.0f + ea), b / (1.0f + eb));
    }
}
__device__ __forceinline__ void sts_vals(uint32_t aBase, int row, int iq,
                                         const uint32_t vals[8]) {
#pragma unroll
    for (int c = 0; c < 2; c++) {
        uint32_t u = row * 16 + ((iq * 2 + c) ^ (row & 7));   // 16B units
        asm volatile("st.shared.v4.b32 [%0], {%1,%2,%3,%4};"
                     :: "r"(aBase + u * 16),
                        "r"(vals[4 * c]), "r"(vals[4 * c + 1]),
                        "r"(vals[4 * c + 2]), "r"(vals[4 * c + 3]) : "memory");
    }
}
__device__ __forceinline__ void cp_B(int t, uint32_t bBase, int tid, int n0) {
    const __half* src; int ldb, ko;
    if (t < BASIS_T) { src = g_Wh;  ldb = KBASE; ko = t * BK; }
    else             { src = g_BWh; ldb = IDIM;  ko = (t - BASIS_T) * BK; }
#pragma unroll
    for (int q = 0; q < 8; q++) {
        int c   = tid + NTHR * q;
        int r   = c >> 4, u16 = c & 15;
        uint32_t u = r * 16 + (u16 ^ (r & 7));
        cp_async16(bBase + u * 16, src + (size_t)(n0 + r) * ldb + ko + u16 * 8);
    }
}

#define LDSM_X4(R, ADDR)                                                        \
    asm volatile("ldmatrix.sync.aligned.m8n8.x4.shared.b16 {%0,%1,%2,%3}, [%4];"\
                 : "=r"((R)[0]), "=r"((R)[1]), "=r"((R)[2]), "=r"((R)[3])       \
                 : "r"(ADDR))

#define MMA16816(ACC, A, B0, B1)                                                \
    asm volatile("mma.sync.aligned.m16n8k16.row.col.f32.f16.f16.f32 "           \
                 "{%0,%1,%2,%3}, {%4,%5,%6,%7}, {%8,%9}, {%0,%1,%2,%3};"        \
                 : "+f"((ACC)[0]), "+f"((ACC)[1]), "+f"((ACC)[2]), "+f"((ACC)[3])\
                 : "r"((A)[0]), "r"((A)[1]), "r"((A)[2]), "r"((A)[3]),          \
                   "r"(B0), "r"(B1))

__global__ void __launch_bounds__(NTHR, 1)
gemm_kernel() {
    extern __shared__ __align__(1024) char sm[];
    const uint32_t sb  = smem_u32(sm);
    const uint32_t sbA = sb;                    // 2 x 16 KB
    const uint32_t sbB = sb + 2 * TILE_A;       // 2 x 64 KB

    const int tid  = threadIdx.x;
    const int lane = tid & 31;
    const int wid  = tid >> 5;                  // 0..15
    const int wm   = wid >> 3;                  // 0..1: 32 rows each
    const int wn   = wid & 7;                   // 0..7: 32 cols each
    const int row  = tid & 63;
    const int iq   = tid >> 6;                  // 0..7

    const int cta  = blockIdx.x;
    int g          = (GTOT * cta) / NCTA;
    const int gend = (GTOT * (cta + 1)) / NCTA;

    while (g < gend) {
        const int tt   = g / NKT;
        const int l0   = g - tt * NKT;
        const int lend = min(NKT, gend - tt * NKT);
        const int m0   = (tt & 63) * BM;
        const int n0   = (tt >> 6) * BN;

        float acc[2][4][4] = {};
        uint32_t vals[8];
        float xv = 0.0f;

        // ---- segment prologue: A(l0) gen+store, B(l0) cp
        if (l0 < BASIS_T) {
            float x0 = g_xT[(size_t)(l0 * 8 + iq) * BATCH + m0 + row];
            gen_basis(x0, vals);
        } else {
            gen_silu16(l0, row, iq, m0, vals);
        }
        sts_vals(sbA + (l0 & 1) * TILE_A, row, iq, vals);
        cp_B(l0, sbB + (l0 & 1) * TILE_BS, tid, n0);
        asm volatile("cp.async.commit_group;");
        if (l0 + 1 < lend && l0 + 1 < BASIS_T)
            xv = g_xT[(size_t)((l0 + 1) * 8 + iq) * BATCH + m0 + row];
        asm volatile("cp.async.wait_group 0;");
        __syncthreads();

        for (int t = l0; t < lend; t++) {
            const uint32_t aB = sbA + (t & 1) * TILE_A;
            const uint32_t bB = sbB + (t & 1) * TILE_BS;

            // 1) B(t+1) into the other buffer
            if (t + 1 < lend) {
                cp_B(t + 1, sbB + ((t + 1) & 1) * TILE_BS, tid, n0);
                asm volatile("cp.async.commit_group;");
            }
            // 2) generate A(t+1) into regs
            if (t + 1 < lend) {
                if (t + 1 < BASIS_T) gen_basis(xv, vals);
                else                 gen_silu16(t + 1, row, iq, m0, vals);
            }

            // 3) MMA over this k-tile (8 x k16 steps)
#pragma unroll
            for (int ks = 0; ks < 8; ks++) {
                const int c16 = ks * 2 + (lane >> 4);
                uint32_t af[2][4], bf[2][4];
#pragma unroll
                for (int mi = 0; mi < 2; mi++) {
                    int r = wm * 32 + mi * 16 + (lane & 15);
                    uint32_t u = r * 16 + (c16 ^ (r & 7));
                    LDSM_X4(af[mi], aB + u * 16);
                }
#pragma unroll
                for (int nj = 0; nj < 2; nj++) {
                    int r = wn * 32 + nj * 16 + (lane & 15);
                    uint32_t u = r * 16 + (c16 ^ (r & 7));
                    LDSM_X4(bf[nj], bB + u * 16);
                }
#pragma unroll
                for (int mi = 0; mi < 2; mi++)
#pragma unroll
                    for (int nj = 0; nj < 2; nj++) {
                        MMA16816(acc[mi][2 * nj],     af[mi], bf[nj][0], bf[nj][2]);
                        MMA16816(acc[mi][2 * nj + 1], af[mi], bf[nj][1], bf[nj][3]);
                    }
            }

            // 4) store A(t+1) into the other A buffer
            if (t + 1 < lend)
                sts_vals(sbA + ((t + 1) & 1) * TILE_A, row, iq, vals);
            // 5) prefetch x for tile t+2
            if (t + 2 < lend && t + 2 < BASIS_T)
                xv = g_xT[(size_t)((t + 2) * 8 + iq) * BATCH + m0 + row];

            asm volatile("cp.async.wait_group 0;");   // B(t+1) resident
            __syncthreads();                          // A(t+1) visible; buffers swap
        }

        // ---- segment epilogue: commit partial sums (fire-and-forget red)
#pragma unroll
        for (int mi = 0; mi < 2; mi++)
#pragma unroll
            for (int ni = 0; ni < 4; ni++) {
                int r = m0 + wm * 32 + mi * 16 + (lane >> 2);
                int c = n0 + wn * 32 + ni * 8 + (lane & 3) * 2;
                red_add(&g_gemm[(size_t)r * ODIM + c],           acc[mi][ni][0]);
                red_add(&g_gemm[(size_t)r * ODIM + c + 1],       acc[mi][ni][1]);
                red_add(&g_gemm[(size_t)(r + 8) * ODIM + c],     acc[mi][ni][2]);
                red_add(&g_gemm[(size_t)(r + 8) * ODIM + c + 1], acc[mi][ni][3]);
            }

        g = tt * NKT + lend;
    }
}

// -------------------- LayerNorm: 1 warp per row, 1024 x 128 --------------
__global__ void ln_kernel(const float* __restrict__ gamma,
                          const float* __restrict__ beta,
                          float* __restrict__ out) {
    int warp = threadIdx.x >> 5, lane = threadIdx.x & 31;
    int row = blockIdx.x * 4 + warp;
    const float4* src = (const float4*)&g_gemm[(size_t)row * ODIM];
    float4 v[4];
    float s = 0.0f, s2 = 0.0f;
#pragma unroll
    for (int i = 0; i < 4; i++) {
        v[i] = src[i * 32 + lane];
        s  += v[i].x + v[i].y + v[i].z + v[i].w;
        s2 += v[i].x*v[i].x + v[i].y*v[i].y + v[i].z*v[i].z + v[i].w*v[i].w;
    }
#pragma unroll
    for (int o = 16; o > 0; o >>= 1) {
        s  += __shfl_xor_sync(0xFFFFFFFFu, s,  o);
        s2 += __shfl_xor_sync(0xFFFFFFFFu, s2, o);
    }
    float mean = s * (1.0f / ODIM);
    float var  = s2 * (1.0f / ODIM) - mean * mean;
    float rstd = rsqrtf(var + 1e-5f);
    const float4* g4 = (const float4*)gamma;
    const float4* b4 = (const float4*)beta;
    float4* dst = (float4*)&out[(size_t)row * ODIM];
#pragma unroll
    for (int i = 0; i < 4; i++) {
        int c4 = i * 32 + lane;
        float4 gm = g4[c4], bt = b4[c4], r;
        r.x = (v[i].x - mean) * rstd * gm.x + bt.x;
        r.y = (v[i].y - mean) * rstd * gm.y + bt.y;
        r.z = (v[i].z - mean) * rstd * gm.z + bt.z;
        r.w = (v[i].w - mean) * rstd * gm.w + bt.w;
        dst[c4] = r;
    }
}

// ---------------------------------------------------------------------------
extern "C" void kernel_launch(void* const* d_in, const int* in_sizes, int n_in,
                              void* d_out, int out_size) {
    const float* x      = (const float*)d_in[0];
    const float* wts    = (const float*)d_in[1];
    const float* base_w = (const float*)d_in[2];
    const float* gamma  = (const float*)d_in[3];
    const float* beta   = (const float*)d_in[4];
    float* out = (float*)d_out;

    prep_all<<<PW_BLOCKS + XT_BLOCKS + ZG_BLOCKS, 256>>>(wts, base_w, x);

    int smem_bytes = 2 * TILE_A + 2 * TILE_BS;   // 160 KB
    cudaFuncSetAttribute(gemm_kernel, cudaFuncAttributeMaxDynamicSharedMemorySize,
                         smem_bytes);
    gemm_kernel<<<NCTA, NTHR, smem_bytes>>>();

    ln_kernel<<<BATCH / 4, 128>>>(gamma, beta, out);
}